// round 16
// baseline (speedup 1.0000x reference)
#include <cuda_runtime.h>
#include <cuda_bf16.h>
#include <math.h>
#include <stdint.h>

#define VERY_NEG (-1e30f)

constexpr int Bz = 128;
constexpr int S  = 256;
constexpr int H  = 256;
constexpr int NH = 8;
constexpr int Dh = 32;
constexpr int C  = 20000;
constexpr int A  = 8;
constexpr int BS = Bz * S;
constexpr int CA = C * A;
constexpr int FF = 4 * H;
constexpr int NODES1 = 25001;
constexpr int QKVN = 3 * H;

// dynamic smem: 3 stages x (A 128x8 + B 128x8) x {h,l}  (permuted kpair layout)
constexpr int AW = 128 * 8;
constexpr int BW = 128 * 8;
constexpr int GSM = 3 * (AW + BW) * 2 * 4;   // 49152 bytes

// ---------------- scratch ------------------------------------------------------
__device__ uint32_t g_eh [(size_t)NODES1 * 128];
__device__ uint32_t g_el [(size_t)NODES1 * 128];
__device__ float    g_s  [CA];
__device__ float    g_dag[(size_t)C * H];
__device__ float    g_xv [(size_t)BS * H];
__device__ float    g_xd [(size_t)BS * H];
__device__ uint32_t g_xvh[(size_t)BS * 128], g_xvl[(size_t)BS * 128];
__device__ uint32_t g_xdh[(size_t)BS * 128], g_xdl[(size_t)BS * 128];
__device__ float    g_qkv[2][(size_t)BS * QKVN];
__device__ uint32_t g_cth[2][(size_t)BS * 128], g_ctl[2][(size_t)BS * 128];
__device__ float    g_t  [2][(size_t)BS * H];
__device__ uint32_t g_th [2][(size_t)BS * 128], g_tl [2][(size_t)BS * 128];
__device__ uint32_t g_fh [2][(size_t)BS * 512], g_fl [2][(size_t)BS * 512];
__device__ float    g_xdo[(size_t)BS * H];
__device__ uint32_t g_wqkvh[2][128 * QKVN], g_wqkvl[2][128 * QKVN];
__device__ uint32_t g_woh [2][128 * 256],  g_wol [2][128 * 256];
__device__ uint32_t g_f1h [2][128 * 1024], g_f1l [2][128 * 1024];
__device__ uint32_t g_f2h [2][512 * 256],  g_f2l [2][512 * 256];
__device__ uint32_t g_w1h [256 * 256],  g_w1l [256 * 256];

// ---------------- helpers ------------------------------------------------------
// permute kpair index within 16-k groups so fragment pairs (c, c+4) are adjacent
__device__ __forceinline__ size_t perm8(size_t L) {
    const int kp = (int)(L & 7);
    return (L & ~(size_t)7) | (size_t)(((kp & 3) << 1) | (kp >> 2));
}

__device__ __forceinline__ void mma_bf16(float* c, const uint32_t* a, const uint32_t* b) {
    asm volatile(
        "mma.sync.aligned.m16n8k16.row.col.f32.bf16.bf16.f32 "
        "{%0,%1,%2,%3}, {%4,%5,%6,%7}, {%8,%9}, {%0,%1,%2,%3};\n"
        : "+f"(c[0]), "+f"(c[1]), "+f"(c[2]), "+f"(c[3])
        : "r"(a[0]), "r"(a[1]), "r"(a[2]), "r"(a[3]),
          "r"(b[0]), "r"(b[1]));
}

__device__ __forceinline__ void split2(float x0, float x1, uint32_t& hi, uint32_t& lo) {
    __nv_bfloat16 h0 = __float2bfloat16_rn(x0);
    __nv_bfloat16 h1 = __float2bfloat16_rn(x1);
    __nv_bfloat16 l0 = __float2bfloat16_rn(x0 - __bfloat162float(h0));
    __nv_bfloat16 l1 = __float2bfloat16_rn(x1 - __bfloat162float(h1));
    hi = ((uint32_t)__bfloat16_as_ushort(h1) << 16) | __bfloat16_as_ushort(h0);
    lo = ((uint32_t)__bfloat16_as_ushort(l1) << 16) | __bfloat16_as_ushort(l0);
}

__device__ __forceinline__ uint32_t packbf(float a, float b) {
    __nv_bfloat162 t = __floats2bfloat162_rn(a, b);
    return *reinterpret_cast<uint32_t*>(&t);
}

#define CP_ASYNC16(dst, src) \
    asm volatile("cp.async.cg.shared.global [%0], [%1], 16;" :: "r"(dst), "l"(src) : "memory")
#define CP_COMMIT()  asm volatile("cp.async.commit_group;" ::: "memory")
#define CP_WAIT0()   asm volatile("cp.async.wait_group 0;" ::: "memory")
#define CP_WAIT1()   asm volatile("cp.async.wait_group 1;" ::: "memory")

__global__ void pack_contig_kernel(const float* __restrict__ src, uint32_t* __restrict__ dh,
                                   uint32_t* __restrict__ dl, int n2)
{
    int idx = blockIdx.x * blockDim.x + threadIdx.x;
    if (idx >= n2) return;
    float2 v = ((const float2*)src)[idx];
    uint32_t h, l;
    split2(v.x, v.y, h, l);
    const size_t d = perm8((size_t)idx);
    dh[d] = h; dl[d] = l;
}

struct PackSeg {
    const float* src;
    uint32_t *dh, *dl;
    int Khalf, Nsrc, Ndst, coff, start;
};
struct PackAll { PackSeg seg[13]; int total; };

// weights [K][Nsrc] fp32 -> n-major permuted packed: dst[(coff+n)*Khalf + perm(kp)]
__global__ void pack_all_kernel(PackAll pa)
{
    int idx = blockIdx.x * blockDim.x + threadIdx.x;
    if (idx >= pa.total) return;
    int si = 0;
    #pragma unroll
    for (int i = 1; i < 13; i++)
        if (idx >= pa.seg[i].start) si = i;
    const PackSeg& sg = pa.seg[si];
    int li = idx - sg.start;
    int kp = li / sg.Nsrc, n = li - kp * sg.Nsrc;
    float a = sg.src[(size_t)(2 * kp) * sg.Nsrc + n];
    float b = sg.src[(size_t)(2 * kp + 1) * sg.Nsrc + n];
    uint32_t h, l;
    split2(a, b, h, l);
    const size_t d = perm8((size_t)(sg.coff + n) * sg.Khalf + kp);
    sg.dh[d] = h;
    sg.dl[d] = l;
}

__global__ void s_init_kernel(float* __restrict__ s, const float* __restrict__ b2)
{
    int idx = blockIdx.x * blockDim.x + threadIdx.x;
    if (idx < CA) s[idx] = b2[0];
}

// ---------------- pointer-pair arg block (z selects encoder) -------------------
struct G2 {
    const uint32_t *Ah0, *Al0, *Bh0, *Bl0;
    const uint32_t *Ah1, *Al1, *Bh1, *Bl1;
    const float *bias0, *bias1, *Res0, *Res1;
    float *Cm0, *Cm1;
    uint32_t *Ch0, *Cl0, *Ch1, *Cl1;
};

// ---------------- split-bf16 tensor GEMM: 3-stage cp.async + LDS.64 frags -----
template <bool RELU, bool BIAS, bool RES, bool GATHER, bool OUTF32, bool SPLIT, bool SCORE>
__global__ __launch_bounds__(256, 2)
void tgemm_kernel(G2 g, const float* __restrict__ w2, float* __restrict__ sout,
                  int M, int N, int K,
                  const int* __restrict__ gl, const int* __restrict__ ga)
{
    extern __shared__ uint32_t dsm[];
    uint32_t* ASH = dsm;                 // [3][128 rows][8]
    uint32_t* ASL = dsm + 3 * AW;
    uint32_t* BSH = dsm + 6 * AW;        // [3][128 cols][8]
    uint32_t* BSL = dsm + 6 * AW + 3 * BW;

    const int z = blockIdx.z;
    const uint32_t* __restrict__ Ah = z ? g.Ah1 : g.Ah0;
    const uint32_t* __restrict__ Al = z ? g.Al1 : g.Al0;
    const uint32_t* __restrict__ Bh = z ? g.Bh1 : g.Bh0;
    const uint32_t* __restrict__ Bl = z ? g.Bl1 : g.Bl0;
    const float* __restrict__ bias  = z ? g.bias1 : g.bias0;
    const float* __restrict__ Res   = z ? g.Res1 : g.Res0;
    float* __restrict__ Cm          = z ? g.Cm1 : g.Cm0;
    uint32_t* __restrict__ Ch       = z ? g.Ch1 : g.Ch0;
    uint32_t* __restrict__ Cl       = z ? g.Cl1 : g.Cl0;

    const int tid  = threadIdx.x;
    const int lane = tid & 31;
    const int wid  = tid >> 5;
    const int warp_m = wid & 3;
    const int warp_n = wid >> 2;
    const int m0 = blockIdx.y * 128, n0 = blockIdx.x * 128;
    const int r = lane >> 2, c = lane & 3;
    const int Khalf = K >> 1;

    // copy mapping: thread -> (row/col, group half)
    const int crow = tid >> 1;             // 0..127 (A row and B col)
    const int ci4  = (tid & 1) << 2;       // 0 or 4 (position within 8-word group)

    int grow_l = 0, grow_a = 0;
    if (GATHER) {
        grow_l = gl[m0 + crow];
        grow_a = ga[m0 + crow];
    }

    uint32_t a_h_dst = (uint32_t)__cvta_generic_to_shared(&ASH[crow * 8 + ci4]);
    uint32_t a_l_dst = (uint32_t)__cvta_generic_to_shared(&ASL[crow * 8 + ci4]);
    uint32_t b_h_dst = (uint32_t)__cvta_generic_to_shared(&BSH[crow * 8 + ci4]);
    uint32_t b_l_dst = (uint32_t)__cvta_generic_to_shared(&BSL[crow * 8 + ci4]);

    float acc[2][8][4] = {};

    auto issue_tile = [&](int buf, int k0) {
        const int kpb = k0 >> 1;
        size_t aaddr;
        if (GATHER) {
            const int src = (k0 < 256) ? grow_l : grow_a;
            aaddr = (size_t)src * 128 + (kpb & 127) + ci4;
        } else {
            aaddr = (size_t)(m0 + crow) * Khalf + kpb + ci4;
        }
        CP_ASYNC16(a_h_dst + buf * (AW * 4), &Ah[aaddr]);
        CP_ASYNC16(a_l_dst + buf * (AW * 4), &Al[aaddr]);
        const size_t baddr = (size_t)(n0 + crow) * Khalf + kpb + ci4;
        CP_ASYNC16(b_h_dst + buf * (BW * 4), &Bh[baddr]);
        CP_ASYNC16(b_l_dst + buf * (BW * 4), &Bl[baddr]);
    };

    const int ntiles = K >> 4;
    issue_tile(0, 0);
    CP_COMMIT();
    if (ntiles > 1) { issue_tile(1, 16); CP_COMMIT(); }

    int cur = 0;
    for (int t = 0; t < ntiles; t++) {
        if (t + 1 < ntiles) CP_WAIT1(); else CP_WAIT0();
        __syncthreads();

        uint32_t a_h[2][4], a_l[2][4], b_h[8][2], b_l[8][2];
        const uint32_t* Ahc = ASH + cur * AW;
        const uint32_t* Alc = ASL + cur * AW;
        const uint32_t* Bhc = BSH + cur * BW;
        const uint32_t* Blc = BSL + cur * BW;
        #pragma unroll
        for (int mt = 0; mt < 2; mt++) {
            const int row = warp_m * 32 + mt * 16 + r;
            uint2 u0 = *(const uint2*)&Ahc[row * 8 + 2 * c];
            uint2 u1 = *(const uint2*)&Ahc[(row + 8) * 8 + 2 * c];
            a_h[mt][0] = u0.x; a_h[mt][1] = u1.x; a_h[mt][2] = u0.y; a_h[mt][3] = u1.y;
            uint2 v0 = *(const uint2*)&Alc[row * 8 + 2 * c];
            uint2 v1 = *(const uint2*)&Alc[(row + 8) * 8 + 2 * c];
            a_l[mt][0] = v0.x; a_l[mt][1] = v1.x; a_l[mt][2] = v0.y; a_l[mt][3] = v1.y;
        }
        #pragma unroll
        for (int nt = 0; nt < 8; nt++) {
            const int col = warp_n * 64 + nt * 8 + r;
            uint2 vh = *(const uint2*)&Bhc[col * 8 + 2 * c];
            b_h[nt][0] = vh.x; b_h[nt][1] = vh.y;
            uint2 vl = *(const uint2*)&Blc[col * 8 + 2 * c];
            b_l[nt][0] = vl.x; b_l[nt][1] = vl.y;
        }

        if (t + 2 < ntiles) {
            int nxt = cur + 2;
            if (nxt >= 3) nxt -= 3;
            issue_tile(nxt, (t + 2) << 4);
            CP_COMMIT();
        }

        #pragma unroll
        for (int mt = 0; mt < 2; mt++)
            #pragma unroll
            for (int nt = 0; nt < 8; nt++) {
                mma_bf16(acc[mt][nt], a_h[mt], b_h[nt]);
                mma_bf16(acc[mt][nt], a_h[mt], b_l[nt]);
                mma_bf16(acc[mt][nt], a_l[mt], b_h[nt]);
            }

        cur = (cur == 2) ? 0 : cur + 1;
    }

    float partial[4] = {0.f, 0.f, 0.f, 0.f};

    #pragma unroll
    for (int mt = 0; mt < 2; mt++) {
        #pragma unroll
        for (int nt = 0; nt < 8; nt++) {
            const int row0 = m0 + warp_m * 32 + mt * 16 + r;
            const int col  = n0 + warp_n * 64 + nt * 8 + 2 * c;
            #pragma unroll
            for (int h = 0; h < 2; h++) {
                float2 v = make_float2(acc[mt][nt][h * 2], acc[mt][nt][h * 2 + 1]);
                if (BIAS) {
                    const float2 bb = *(const float2*)&bias[col];
                    v.x += bb.x; v.y += bb.y;
                }
                if (RELU) { v.x = fmaxf(v.x, 0.f); v.y = fmaxf(v.y, 0.f); }
                const int row = row0 + h * 8;
                const size_t off = (size_t)row * N + col;
                if (RES) {
                    const float2 rr = *(const float2*)&Res[off];
                    v.x += rr.x; v.y += rr.y;
                }
                if (SCORE) {
                    const float2 ww = *(const float2*)&w2[col];
                    partial[mt * 2 + h] += v.x * ww.x + v.y * ww.y;
                }
                if (OUTF32) *(float2*)&Cm[off] = v;
                if (SPLIT) {
                    uint32_t hw, lw;
                    split2(v.x, v.y, hw, lw);
                    const size_t po = perm8((size_t)row * (N >> 1) + (col >> 1));
                    Ch[po] = hw;
                    Cl[po] = lw;
                }
            }
        }
    }

    if (SCORE) {
        #pragma unroll
        for (int mt = 0; mt < 2; mt++)
            #pragma unroll
            for (int h = 0; h < 2; h++) {
                float p = partial[mt * 2 + h];
                p += __shfl_xor_sync(0xffffffffu, p, 1);
                p += __shfl_xor_sync(0xffffffffu, p, 2);
                if ((lane & 3) == 0) {
                    const int row = m0 + warp_m * 32 + mt * 16 + r + h * 8;
                    atomicAdd(&sout[row], p);
                }
            }
    }
}

// ---------------- DAG softmax + weighted ancestor sum --------------------------
__global__ void dag_softmax_kernel(const float* __restrict__ s, const float* __restrict__ mask,
                                   const int* __restrict__ anc, const float* __restrict__ emb,
                                   float* __restrict__ dag)
{
    int gw = (blockIdx.x * blockDim.x + threadIdx.x) >> 5;
    int lane = threadIdx.x & 31;
    if (gw >= C) return;
    float sv = -3.0e38f;
    int av = 0;
    if (lane < 8) {
        float m = mask[gw * 8 + lane];
        sv = s[gw * 8 + lane] + (1.f - m) * VERY_NEG;
        av = anc[gw * 8 + lane];
    }
    float mx = sv;
    #pragma unroll
    for (int off = 4; off; off >>= 1) mx = fmaxf(mx, __shfl_xor_sync(0xffffffffu, mx, off));
    float e = (lane < 8) ? __expf(sv - mx) : 0.f;
    float su = e;
    #pragma unroll
    for (int off = 4; off; off >>= 1) su += __shfl_xor_sync(0xffffffffu, su, off);
    float wv = e / su;
    float w8[8];
    int   a8[8];
    #pragma unroll
    for (int a = 0; a < 8; a++) {
        w8[a] = __shfl_sync(0xffffffffu, wv, a);
        a8[a] = __shfl_sync(0xffffffffu, av, a);
    }
    const float4* e4 = (const float4*)emb;
    #pragma unroll
    for (int rep = 0; rep < 2; rep++) {
        int f4i = lane + rep * 32;
        float4 acc = make_float4(0.f, 0.f, 0.f, 0.f);
        #pragma unroll
        for (int a = 0; a < 8; a++) {
            float4 v = e4[(size_t)a8[a] * 64 + f4i];
            acc.x = fmaf(w8[a], v.x, acc.x);
            acc.y = fmaf(w8[a], v.y, acc.y);
            acc.z = fmaf(w8[a], v.z, acc.z);
            acc.w = fmaf(w8[a], v.w, acc.w);
        }
        ((float4*)dag)[(size_t)gw * 64 + f4i] = acc;
    }
}

__global__ void embed_gather_kernel(const int* __restrict__ ids, const float* __restrict__ embw,
                                    const float* __restrict__ dag,
                                    float* __restrict__ xv, float* __restrict__ xd,
                                    uint32_t* __restrict__ xvh, uint32_t* __restrict__ xvl,
                                    uint32_t* __restrict__ xdh, uint32_t* __restrict__ xdl)
{
    int idx = blockIdx.x * blockDim.x + threadIdx.x;
    if (idx >= BS * 64) return;
    int bs = idx >> 6, h4 = idx & 63;
    int id = ids[bs];
    float4 vv = ((const float4*)embw)[(size_t)id * 64 + h4];
    ((float4*)xv)[(size_t)bs * 64 + h4] = vv;
    float4 dv = make_float4(0.f, 0.f, 0.f, 0.f);
    if (id > 0) dv = ((const float4*)dag)[(size_t)(id - 1) * 64 + h4];
    ((float4*)xd)[(size_t)bs * 64 + h4] = dv;

    const size_t base = (size_t)bs * 128 + h4 * 2;
    const size_t d0 = perm8(base), d1 = perm8(base + 1);
    uint32_t h0, l0, h1, l1;
    split2(vv.x, vv.y, h0, l0);
    split2(vv.z, vv.w, h1, l1);
    xvh[d0] = h0; xvh[d1] = h1;
    xvl[d0] = l0; xvl[d1] = l1;
    split2(dv.x, dv.y, h0, l0);
    split2(dv.z, dv.w, h1, l1);
    xdh[d0] = h0; xdh[d1] = h1;
    xdl[d0] = l0; xdl[d1] = l1;
}

// ---------------- MMA flash attention, 16 q/warp, 32-key chunks ----------------
struct A2 {
    const float *qkv0, *qkv1;
    uint32_t *h0, *l0, *h1, *l1;
};

__global__ __launch_bounds__(256)
void attention_kernel(A2 g, const float* __restrict__ cmask)
{
    __shared__ float    madd[S];
    __shared__ uint32_t Ksh[16 * 40], Ksl[16 * 40];
    __shared__ uint32_t Vsh[16 * 40], Vsl[16 * 40];

    const int h = blockIdx.x, b = blockIdx.y, z = blockIdx.z;
    const int enc = z & 1, qh2 = z >> 1;
    const float* __restrict__ QKV = enc ? g.qkv1 : g.qkv0;
    uint32_t* __restrict__ cth = enc ? g.h1 : g.h0;
    uint32_t* __restrict__ ctl = enc ? g.l1 : g.l0;
    const int tid = threadIdx.x, w = tid >> 5, lane = tid & 31;
    const int gg = lane >> 2, t = lane & 3;
    const size_t rowbase = (size_t)b * S * QKVN;
    const int qo = h * Dh, ko = H + h * Dh, vo = 2 * H + h * Dh;
    const float scale = rsqrtf(32.0f);

    madd[tid] = (1.0f - cmask[b * S + tid]) * VERY_NEG;

    const int rA = qh2 * 128 + w * 16 + gg, rB = rA + 8;
    uint32_t qh[2][4], ql[2][4];
    {
        const float* qA = &QKV[rowbase + (size_t)rA * QKVN + qo];
        const float* qB = &QKV[rowbase + (size_t)rB * QKVN + qo];
        #pragma unroll
        for (int kc = 0; kc < 2; kc++) {
            float2 v0 = *(const float2*)&qA[16 * kc + 2 * t];
            float2 v1 = *(const float2*)&qB[16 * kc + 2 * t];
            float2 v2 = *(const float2*)&qA[16 * kc + 2 * t + 8];
            float2 v3 = *(const float2*)&qB[16 * kc + 2 * t + 8];
            split2(v0.x * scale, v0.y * scale, qh[kc][0], ql[kc][0]);
            split2(v1.x * scale, v1.y * scale, qh[kc][1], ql[kc][1]);
            split2(v2.x * scale, v2.y * scale, qh[kc][2], ql[kc][2]);
            split2(v3.x * scale, v3.y * scale, qh[kc][3], ql[kc][3]);
        }
    }

    float O[4][4] = {};
    float m0 = -INFINITY, m1 = -INFINITY, l0 = 0.f, l1 = 0.f;

    for (int ch = 0; ch < 8; ch++) {
        __syncthreads();
        {
            const int key = tid >> 3;
            const int dh4 = (tid & 7) << 2;
            const float* kp_ = &QKV[rowbase + (size_t)(ch * 32 + key) * QKVN + ko + dh4];
            float4 kv = *(const float4*)kp_;
            const int dp = dh4 >> 1;
            uint32_t hh, ll;
            split2(kv.x, kv.y, hh, ll); Ksh[dp * 40 + key] = hh;       Ksl[dp * 40 + key] = ll;
            split2(kv.z, kv.w, hh, ll); Ksh[(dp + 1) * 40 + key] = hh; Ksl[(dp + 1) * 40 + key] = ll;

            const float* vp_ = &QKV[rowbase + (size_t)(ch * 32 + key) * QKVN + vo + dh4];
            float4 vv = *(const float4*)vp_;
            float va[4] = {vv.x, vv.y, vv.z, vv.w};
            const int kp2 = key >> 1, hf = key & 1;
            #pragma unroll
            for (int d = 0; d < 4; d++) {
                __nv_bfloat16 hb = __float2bfloat16_rn(va[d]);
                __nv_bfloat16 lb = __float2bfloat16_rn(va[d] - __bfloat162float(hb));
                ((uint16_t*)&Vsh[kp2 * 40 + dh4 + d])[hf] = __bfloat16_as_ushort(hb);
                ((uint16_t*)&Vsl[kp2 * 40 + dh4 + d])[hf] = __bfloat16_as_ushort(lb);
            }
        }
        __syncthreads();

        float Sc[4][4] = {};
        #pragma unroll
        for (int nt = 0; nt < 4; nt++) {
            #pragma unroll
            for (int kc = 0; kc < 2; kc++) {
                uint32_t bh[2], bl[2];
                bh[0] = Ksh[(8 * kc + t) * 40 + 8 * nt + gg];
                bh[1] = Ksh[(8 * kc + t + 4) * 40 + 8 * nt + gg];
                bl[0] = Ksl[(8 * kc + t) * 40 + 8 * nt + gg];
                bl[1] = Ksl[(8 * kc + t + 4) * 40 + 8 * nt + gg];
                mma_bf16(Sc[nt], qh[kc], bh);
                mma_bf16(Sc[nt], qh[kc], bl);
                mma_bf16(Sc[nt], ql[kc], bh);
            }
        }

        float mx0 = -INFINITY, mx1 = -INFINITY;
        #pragma unroll
        for (int nt = 0; nt < 4; nt++) {
            const int keyb = ch * 32 + 8 * nt + 2 * t;
            Sc[nt][0] += madd[keyb];
            Sc[nt][1] += madd[keyb + 1];
            Sc[nt][2] += madd[keyb];
            Sc[nt][3] += madd[keyb + 1];
            mx0 = fmaxf(mx0, fmaxf(Sc[nt][0], Sc[nt][1]));
            mx1 = fmaxf(mx1, fmaxf(Sc[nt][2], Sc[nt][3]));
        }
        mx0 = fmaxf(mx0, __shfl_xor_sync(0xffffffffu, mx0, 1));
        mx0 = fmaxf(mx0, __shfl_xor_sync(0xffffffffu, mx0, 2));
        mx1 = fmaxf(mx1, __shfl_xor_sync(0xffffffffu, mx1, 1));
        mx1 = fmaxf(mx1, __shfl_xor_sync(0xffffffffu, mx1, 2));
        const float mn0 = fmaxf(m0, mx0);
        const float mn1 = fmaxf(m1, mx1);
        const float c0 = __expf(m0 - mn0);
        const float c1 = __expf(m1 - mn1);
        float ls0 = 0.f, ls1 = 0.f;
        #pragma unroll
        for (int nt = 0; nt < 4; nt++) {
            float p0 = __expf(Sc[nt][0] - mn0);
            float p1 = __expf(Sc[nt][1] - mn0);
            float p2 = __expf(Sc[nt][2] - mn1);
            float p3 = __expf(Sc[nt][3] - mn1);
            ls0 += p0 + p1;
            ls1 += p2 + p3;
            Sc[nt][0] = p0; Sc[nt][1] = p1; Sc[nt][2] = p2; Sc[nt][3] = p3;
        }
        ls0 += __shfl_xor_sync(0xffffffffu, ls0, 1);
        ls0 += __shfl_xor_sync(0xffffffffu, ls0, 2);
        ls1 += __shfl_xor_sync(0xffffffffu, ls1, 1);
        ls1 += __shfl_xor_sync(0xffffffffu, ls1, 2);
        l0 = l0 * c0 + ls0;
        l1 = l1 * c1 + ls1;
        m0 = mn0;
        m1 = mn1;
        #pragma unroll
        for (int nt = 0; nt < 4; nt++) {
            O[nt][0] *= c0; O[nt][1] *= c0;
            O[nt][2] *= c1; O[nt][3] *= c1;
        }

        uint32_t pa_[2][4];
        #pragma unroll
        for (int kc = 0; kc < 2; kc++) {
            pa_[kc][0] = packbf(Sc[2 * kc][0],     Sc[2 * kc][1]);
            pa_[kc][1] = packbf(Sc[2 * kc][2],     Sc[2 * kc][3]);
            pa_[kc][2] = packbf(Sc[2 * kc + 1][0], Sc[2 * kc + 1][1]);
            pa_[kc][3] = packbf(Sc[2 * kc + 1][2], Sc[2 * kc + 1][3]);
        }

        #pragma unroll
        for (int kc = 0; kc < 2; kc++) {
            #pragma unroll
            for (int nt = 0; nt < 4; nt++) {
                uint32_t bh[2], bl[2];
                bh[0] = Vsh[(8 * kc + t) * 40 + 8 * nt + gg];
                bh[1] = Vsh[(8 * kc + t + 4) * 40 + 8 * nt + gg];
                bl[0] = Vsl[(8 * kc + t) * 40 + 8 * nt + gg];
                bl[1] = Vsl[(8 * kc + t + 4) * 40 + 8 * nt + gg];
                mma_bf16(O[nt], pa_[kc], bh);
                mma_bf16(O[nt], pa_[kc], bl);
            }
        }
    }

    const float i0 = 1.0f / l0;
    const float i1 = 1.0f / l1;
    const size_t p0 = (size_t)(b * S + rA) * 128 + h * 16;
    const size_t p1 = (size_t)(b * S + rB) * 128 + h * 16;
    #pragma unroll
    for (int nt = 0; nt < 4; nt++) {
        uint32_t hw, lw;
        const size_t d0 = perm8(p0 + 4 * nt + t);
        split2(O[nt][0] * i0, O[nt][1] * i0, hw, lw);
        cth[d0] = hw;
        ctl[d0] = lw;
        const size_t d1 = perm8(p1 + 4 * nt + t);
        split2(O[nt][2] * i1, O[nt][3] * i1, hw, lw);
        cth[d1] = hw;
        ctl[d1] = lw;
    }
}

// ---------------- pooling ------------------------------------------------------
__global__ void pool_kernel(const float* __restrict__ x, const float* __restrict__ cmask,
                            const float* __restrict__ pw, const float* __restrict__ pb,
                            float* __restrict__ out)
{
    __shared__ float spw[H];
    __shared__ float sc[S];
    __shared__ float red[8];
    const int b = blockIdx.x, tid = threadIdx.x;
    const int lane = tid & 31, w = tid >> 5;
    spw[tid] = pw[tid];
    __syncthreads();

    for (int row = w; row < S; row += 8) {
        const float* xp = &x[((size_t)b * S + row) * H];
        float4 a0 = *(const float4*)&xp[lane * 4];
        float4 a1 = *(const float4*)&xp[128 + lane * 4];
        float acc = a0.x * spw[lane * 4 + 0] + a0.y * spw[lane * 4 + 1]
                  + a0.z * spw[lane * 4 + 2] + a0.w * spw[lane * 4 + 3]
                  + a1.x * spw[128 + lane * 4 + 0] + a1.y * spw[128 + lane * 4 + 1]
                  + a1.z * spw[128 + lane * 4 + 2] + a1.w * spw[128 + lane * 4 + 3];
        #pragma unroll
        for (int off = 16; off; off >>= 1) acc += __shfl_xor_sync(0xffffffffu, acc, off);
        if (lane == 0)
            sc[row] = acc + pb[0] + (1.f - cmask[b * S + row]) * VERY_NEG;
    }
    __syncthreads();

    float v = sc[tid];
    float mx = v;
    #pragma unroll
    for (int off = 16; off; off >>= 1) mx = fmaxf(mx, __shfl_xor_sync(0xffffffffu, mx, off));
    if (lane == 0) red[w] = mx;
    __syncthreads();
    float bm = red[0];
    #pragma unroll
    for (int i = 1; i < 8; i++) bm = fmaxf(bm, red[i]);
    __syncthreads();
    float e = __expf(v - bm);
    float su = e;
    #pragma unroll
    for (int off = 16; off; off >>= 1) su += __shfl_xor_sync(0xffffffffu, su, off);
    if (lane == 0) red[w] = su;
    __syncthreads();
    float tot = 0.f;
    #pragma unroll
    for (int i = 0; i < 8; i++) tot += red[i];
    sc[tid] = e / tot;
    __syncthreads();

    float acc = 0.f;
    for (int ss = 0; ss < S; ss++)
        acc = fmaf(sc[ss], x[((size_t)b * S + ss) * H + tid], acc);
    out[(size_t)b * H + tid] = acc;
}

// ---------------- host ----------------------------------------------------------
extern "C" void kernel_launch(void* const* d_in, const int* in_sizes, int n_in,
                              void* d_out, int out_size)
{
    const int*   input_ids   = (const int*)d_in[0];
    const float* code_mask   = (const float*)d_in[1];
    const int*   dx_leaves   = (const int*)d_in[2];
    const int*   dx_anc      = (const int*)d_in[3];
    const float* dx_mask     = (const float*)d_in[4];
    const float* embed_init  = (const float*)d_in[5];
    const float* embed_inp   = (const float*)d_in[6];
    const float* attn_w1     = (const float*)d_in[7];
    const float* attn_b1     = (const float*)d_in[8];
    const float* attn_w2     = (const float*)d_in[9];
    const float* attn_b2     = (const float*)d_in[10];
    const float* pool_w      = (const float*)d_in[11];
    const float* pool_b      = (const float*)d_in[12];
    const float* enc_w[2][8];
    for (int z = 0; z < 2; z++)
        for (int j = 0; j < 8; j++)
            enc_w[z][j] = (const float*)d_in[13 + z * 8 + j];
    float* out = (float*)d_out;

    uint32_t *eh, *el, *xvh, *xvl, *xdh, *xdl, *w1h, *w1l;
    uint32_t *cth[2], *ctl[2], *th[2], *tl[2], *fh[2], *fl[2];
    uint32_t *wqkvh[2], *wqkvl[2], *woh[2], *wol[2], *f1h[2], *f1l[2], *f2h[2], *f2l[2];
    float *s, *dag, *xv, *xd, *xdo, *qkv[2], *t[2];
    {
        char* p;
        cudaGetSymbolAddress((void**)&eh, g_eh);   cudaGetSymbolAddress((void**)&el, g_el);
        cudaGetSymbolAddress((void**)&s, g_s);     cudaGetSymbolAddress((void**)&dag, g_dag);
        cudaGetSymbolAddress((void**)&xv, g_xv);   cudaGetSymbolAddress((void**)&xd, g_xd);
        cudaGetSymbolAddress((void**)&xvh, g_xvh); cudaGetSymbolAddress((void**)&xvl, g_xvl);
        cudaGetSymbolAddress((void**)&xdh, g_xdh); cudaGetSymbolAddress((void**)&xdl, g_xdl);
        cudaGetSymbolAddress((void**)&xdo, g_xdo);
        cudaGetSymbolAddress((void**)&w1h, g_w1h); cudaGetSymbolAddress((void**)&w1l, g_w1l);
        cudaGetSymbolAddress((void**)&p, g_qkv);   qkv[0] = (float*)p;    qkv[1] = qkv[0] + (size_t)BS * QKVN;
        cudaGetSymbolAddress((void**)&p, g_t);     t[0] = (float*)p;      t[1] = t[0] + (size_t)BS * H;
        cudaGetSymbolAddress((void**)&p, g_cth);   cth[0] = (uint32_t*)p; cth[1] = cth[0] + (size_t)BS * 128;
        cudaGetSymbolAddress((void**)&p, g_ctl);   ctl[0] = (uint32_t*)p; ctl[1] = ctl[0] + (size_t)BS * 128;
        cudaGetSymbolAddress((void**)&p, g_th);    th[0] = (uint32_t*)p;  th[1] = th[0] + (size_t)BS * 128;
        cudaGetSymbolAddress((void**)&p, g_tl);    tl[0] = (uint32_t*)p;  tl[1] = tl[0] + (size_t)BS * 128;
        cudaGetSymbolAddress((void**)&p, g_fh);    fh[0] = (uint32_t*)p;  fh[1] = fh[0] + (size_t)BS * 512;
        cudaGetSymbolAddress((void**)&p, g_fl);    fl[0] = (uint32_t*)p;  fl[1] = fl[0] + (size_t)BS * 512;
        cudaGetSymbolAddress((void**)&p, g_wqkvh); wqkvh[0] = (uint32_t*)p; wqkvh[1] = wqkvh[0] + 128 * QKVN;
        cudaGetSymbolAddress((void**)&p, g_wqkvl); wqkvl[0] = (uint32_t*)p; wqkvl[1] = wqkvl[0] + 128 * QKVN;
        cudaGetSymbolAddress((void**)&p, g_woh);   woh[0] = (uint32_t*)p;   woh[1] = woh[0] + 128 * 256;
        cudaGetSymbolAddress((void**)&p, g_wol);   wol[0] = (uint32_t*)p;   wol[1] = wol[0] + 128 * 256;
        cudaGetSymbolAddress((void**)&p, g_f1h);   f1h[0] = (uint32_t*)p;   f1h[1] = f1h[0] + 128 * 1024;
        cudaGetSymbolAddress((void**)&p, g_f1l);   f1l[0] = (uint32_t*)p;   f1l[1] = f1l[0] + 128 * 1024;
        cudaGetSymbolAddress((void**)&p, g_f2h);   f2h[0] = (uint32_t*)p;   f2h[1] = f2h[0] + 512 * 256;
        cudaGetSymbolAddress((void**)&p, g_f2l);   f2l[0] = (uint32_t*)p;   f2l[1] = f2l[0] + 512 * 256;
    }

    cudaFuncSetAttribute(tgemm_kernel<true, true, false, true, false, false, true>,
                         cudaFuncAttributeMaxDynamicSharedMemorySize, GSM);
    cudaFuncSetAttribute(tgemm_kernel<false, false, false, false, true, false, false>,
                         cudaFuncAttributeMaxDynamicSharedMemorySize, GSM);
    cudaFuncSetAttribute(tgemm_kernel<false, false, true, false, true, true, false>,
                         cudaFuncAttributeMaxDynamicSharedMemorySize, GSM);
    cudaFuncSetAttribute(tgemm_kernel<true, true, false, false, false, true, false>,
                         cudaFuncAttributeMaxDynamicSharedMemorySize, GSM);
    cudaFuncSetAttribute(tgemm_kernel<false, true, true, false, true, false, false>,
                         cudaFuncAttributeMaxDynamicSharedMemorySize, GSM);

    const int PT = 256;
    pack_contig_kernel<<<(NODES1 * 128 + PT - 1) / PT, PT>>>(embed_init, eh, el, NODES1 * 128);
    s_init_kernel<<<(CA + PT - 1) / PT, PT>>>(s, attn_b2);

    // merged weight packing (n-major, permuted)
    {
        PackAll pa{};
        int cur = 0, si = 0;
        auto add = [&](const float* src, uint32_t* dh, uint32_t* dl,
                       int Khalf, int Nsrc, int coff) {
            pa.seg[si] = {src, dh, dl, Khalf, Nsrc, 0, coff, cur};
            cur += Khalf * Nsrc;
            si++;
        };
        add(attn_w1, w1h, w1l, 256, 256, 0);
        for (int z = 0; z < 2; z++) {
            add(enc_w[z][0], wqkvh[z], wqkvl[z], 128, 256, 0);
            add(enc_w[z][1], wqkvh[z], wqkvl[z], 128, 256, 256);
            add(enc_w[z][2], wqkvh[z], wqkvl[z], 128, 256, 512);
            add(enc_w[z][3], woh[z], wol[z], 128, 256, 0);
            add(enc_w[z][4], f1h[z], f1l[z], 128, 1024, 0);
            add(enc_w[z][6], f2h[z], f2l[z], 512, 256, 0);
        }
        pa.total = cur;
        pack_all_kernel<<<(cur + PT - 1) / PT, PT>>>(pa);
    }

    // DAG MLP: gathered A + fused score
    {
        G2 g{};
        g.Ah0 = g.Ah1 = eh;  g.Al0 = g.Al1 = el;
        g.Bh0 = g.Bh1 = w1h; g.Bl0 = g.Bl1 = w1l;
        g.bias0 = g.bias1 = attn_b1;
        tgemm_kernel<true, true, false, true, false, false, true><<<dim3(2, CA / 128, 1), 256, GSM>>>(
            g, attn_w2, s, CA, 256, 512, dx_leaves, dx_anc);
    }
    dag_softmax_kernel<<<C / 8, 256>>>(s, dx_mask, dx_anc, embed_init, dag);
    embed_gather_kernel<<<(BS * 64 + PT - 1) / PT, PT>>>(input_ids, embed_inp, dag,
                                                         xv, xd, xvh, xvl, xdh, xdl);

    // --- both encoders batched over gridDim.z ---
    {
        G2 g{};
        g.Ah0 = xvh; g.Al0 = xvl; g.Ah1 = xdh; g.Al1 = xdl;
        g.Bh0 = wqkvh[0]; g.Bl0 = wqkvl[0]; g.Bh1 = wqkvh[1]; g.Bl1 = wqkvl[1];
        g.Cm0 = qkv[0]; g.Cm1 = qkv[1];
        tgemm_kernel<false, false, false, false, true, false, false><<<dim3(QKVN / 128, BS / 128, 2), 256, GSM>>>(
            g, nullptr, nullptr, BS, QKVN, H, nullptr, nullptr);
    }
    {
        A2 a{qkv[0], qkv[1], cth[0], ctl[0], cth[1], ctl[1]};
        attention_kernel<<<dim3(NH, Bz, 4), 256>>>(a, code_mask);
    }
    {
        G2 g{};
        g.Ah0 = cth[0]; g.Al0 = ctl[0]; g.Ah1 = cth[1]; g.Al1 = ctl[1];
        g.Bh0 = woh[0]; g.Bl0 = wol[0]; g.Bh1 = woh[1]; g.Bl1 = wol[1];
        g.Res0 = xv; g.Res1 = xd;
        g.Cm0 = t[0]; g.Cm1 = t[1];
        g.Ch0 = th[0]; g.Cl0 = tl[0]; g.Ch1 = th[1]; g.Cl1 = tl[1];
        tgemm_kernel<false, false, true, false, true, true, false><<<dim3(2, BS / 128, 2), 256, GSM>>>(
            g, nullptr, nullptr, BS, H, H, nullptr, nullptr);
    }
    {
        G2 g{};
        g.Ah0 = th[0]; g.Al0 = tl[0]; g.Ah1 = th[1]; g.Al1 = tl[1];
        g.Bh0 = f1h[0]; g.Bl0 = f1l[0]; g.Bh1 = f1h[1]; g.Bl1 = f1l[1];
        g.bias0 = enc_w[0][5]; g.bias1 = enc_w[1][5];
        g.Ch0 = fh[0]; g.Cl0 = fl[0]; g.Ch1 = fh[1]; g.Cl1 = fl[1];
        tgemm_kernel<true, true, false, false, false, true, false><<<dim3(FF / 128, BS / 128, 2), 256, GSM>>>(
            g, nullptr, nullptr, BS, FF, H, nullptr, nullptr);
    }
    {
        G2 g{};
        g.Ah0 = fh[0]; g.Al0 = fl[0]; g.Ah1 = fh[1]; g.Al1 = fl[1];
        g.Bh0 = f2h[0]; g.Bl0 = f2l[0]; g.Bh1 = f2h[1]; g.Bl1 = f2l[1];
        g.bias0 = enc_w[0][7]; g.bias1 = enc_w[1][7];
        g.Res0 = t[0]; g.Res1 = t[1];
        g.Cm0 = out; g.Cm1 = xdo;
        tgemm_kernel<false, true, true, false, true, false, false><<<dim3(2, BS / 128, 2), 256, GSM>>>(
            g, nullptr, nullptr, BS, H, FF, nullptr, nullptr);
    }

    pool_kernel<<<Bz, 256>>>(xdo, code_mask, pool_w, pool_b, out + (size_t)BS * H);
}